// round 1
// baseline (speedup 1.0000x reference)
#include <cuda_runtime.h>
#include <math.h>

// ---------------------------------------------------------------------------
// SpatialDecoderGMM: N=100k nodes, E=1.6M edges, F=1, H=64, K=32
// Pipeline:
//   1. x_in = [x | x_hat_1 | h] @ W_in + b_in            -> g_xin [N,64]
//   2. bidirectional normalized diffusion over edges      -> g_ofob [N,128]
//   3. out64 = g_ofob @ W_filt + b_filt ; out1=[out64|h]  -> g_out1 [N,128]
//   4. heads = out1 @ [W_mu|W_sigma|W_pi] + b             -> g_raw [N,96]
//   5. softplus(sigma), softmax(pi)                       -> gmm_out
// Output layout (concat of reference tuple): gmm_out[N*96] | out1[N*128] | h[N*64]
// ---------------------------------------------------------------------------

#define MAXN 100000
#define MAXE 1600000

__device__ __align__(16) float g_xin [MAXN * 64];
__device__ __align__(16) float g_ofob[MAXN * 128];   // [out_f(64) | out_b(64)] per node
__device__ __align__(16) float g_out1[MAXN * 128];   // [out64(64) | h(64)] per node
__device__ __align__(16) float g_raw [MAXN * 96];    // raw head logits
__device__ __align__(16) float g_degf[MAXN];
__device__ __align__(16) float g_degb[MAXN];
__device__ __align__(16) float g_Whead[128 * 96];
__device__ __align__(16) float g_bhead[96];

// ---------------------------------------------------------------------------
// Pack the three head weight matrices into one [128,96] matrix (cols: mu|sigma|pi)
// ---------------------------------------------------------------------------
__global__ void pack_head_kernel(const float* __restrict__ Wmu, const float* __restrict__ bmu,
                                 const float* __restrict__ Wsg, const float* __restrict__ bsg,
                                 const float* __restrict__ Wpi, const float* __restrict__ bpi) {
    int idx = blockIdx.x * blockDim.x + threadIdx.x;
    if (idx < 128 * 32) {
        int i = idx >> 5, k = idx & 31;
        g_Whead[i * 96 + k]      = Wmu[idx];
        g_Whead[i * 96 + 32 + k] = Wsg[idx];
        g_Whead[i * 96 + 64 + k] = Wpi[idx];
    }
    if (idx < 32) {
        g_bhead[idx]      = bmu[idx];
        g_bhead[32 + idx] = bsg[idx];
        g_bhead[64 + idx] = bpi[idx];
    }
}

// ---------------------------------------------------------------------------
// Input projection: x_in[N,161] @ W_in[161,64] + b_in -> g_xin[N,64]
// Also copies h into g_out1 upper half (cols 64..127).
// Block: 256 threads, 32 nodes per block. Each thread: 2 nodes x 4 cols.
// ---------------------------------------------------------------------------
__global__ void proj_kernel(const float* __restrict__ x, const float* __restrict__ xh,
                            const float* __restrict__ h, const float* __restrict__ Win,
                            const float* __restrict__ bin, int N) {
    extern __shared__ float sm[];
    float* sW = sm;                 // 161*64
    float* sB = sW + 161 * 64;      // 64
    float* sX = sB + 64;            // 32*163 (stride 163 => conflict-free)

    const int tid = threadIdx.x;
    for (int idx = tid; idx < 161 * 64; idx += 256) sW[idx] = Win[idx];
    if (tid < 64) sB[tid] = bin[tid];

    int node0 = blockIdx.x * 32;
    for (int idx = tid; idx < 32 * 161; idx += 256) {
        int n = idx / 161, i = idx % 161;
        int g = node0 + n;
        float v = 0.f;
        if (g < N) {
            if (i == 0)       v = x[g];
            else if (i < 97)  v = xh[(size_t)g * 96 + (i - 1)];
            else              v = h[(size_t)g * 64 + (i - 97)];
        }
        sX[n * 163 + i] = v;
    }
    __syncthreads();

    // copy h slice into g_out1 upper half
    for (int idx = tid; idx < 32 * 64; idx += 256) {
        int n = idx >> 6, j = idx & 63;
        int g = node0 + n;
        if (g < N) g_out1[(size_t)g * 128 + 64 + j] = sX[n * 163 + 97 + j];
    }

    int c4 = tid & 15;       // 16 quads = 64 cols
    int sub = tid >> 4;      // 16 subs, 2 nodes each
    const float4* sW4 = reinterpret_cast<const float4*>(sW);
    float4 bb = reinterpret_cast<const float4*>(sB)[c4];
    float4 acc0 = bb, acc1 = bb;
    int n0 = sub * 2, n1 = n0 + 1;

    #pragma unroll 4
    for (int i = 0; i < 161; i++) {
        float4 w = sW4[i * 16 + c4];
        float x0 = sX[n0 * 163 + i];
        float x1 = sX[n1 * 163 + i];
        acc0.x += x0 * w.x; acc0.y += x0 * w.y; acc0.z += x0 * w.z; acc0.w += x0 * w.w;
        acc1.x += x1 * w.x; acc1.y += x1 * w.y; acc1.z += x1 * w.z; acc1.w += x1 * w.w;
    }
    int g0 = node0 + n0, g1 = node0 + n1;
    if (g0 < N) reinterpret_cast<float4*>(g_xin)[(size_t)g0 * 16 + c4] = acc0;
    if (g1 < N) reinterpret_cast<float4*>(g_xin)[(size_t)g1 * 16 + c4] = acc1;
}

// ---------------------------------------------------------------------------
// Weighted degree accumulation (self-loops removed)
// ---------------------------------------------------------------------------
__global__ void degree_kernel(const int* __restrict__ ei, const float* __restrict__ ew, int E) {
    int e = blockIdx.x * blockDim.x + threadIdx.x;
    if (e >= E) return;
    int s = ei[e], t = ei[E + e];
    if (s == t) return;
    float w = ew[e];
    if (w == 0.f) return;
    atomicAdd(&g_degf[t], w);
    atomicAdd(&g_degb[s], w);
}

__device__ __forceinline__ void red_add4(float* p, float a, float b, float c, float d) {
    asm volatile(
        "{\n\t"
        ".reg .u64 pg;\n\t"
        "cvta.to.global.u64 pg, %0;\n\t"
        "red.global.add.v4.f32 [pg], {%1, %2, %3, %4};\n\t"
        "}"
        :: "l"(p), "f"(a), "f"(b), "f"(c), "f"(d) : "memory");
}

// ---------------------------------------------------------------------------
// Scatter: per edge, both diffusion directions.
// 16 lanes per edge, each lane owns one float4 chunk (64 feats = 16 quads).
//   out_f[tgt] += (w/deg_f[tgt]) * xin[src]
//   out_b[src] += (w/deg_b[src]) * xin[tgt]
// ---------------------------------------------------------------------------
__global__ void scatter_kernel(const int* __restrict__ ei, const float* __restrict__ ew, int E) {
    int tid = threadIdx.x;
    int e = blockIdx.x * 16 + (tid >> 4);
    if (e >= E) return;
    int l = tid & 15;
    int s = ei[e], t = ei[E + e];
    if (s == t) return;
    float w = ew[e];
    if (w == 0.f) return;

    float df = g_degf[t];
    float db = g_degb[s];
    float wf = w / (df > 0.f ? df : 1.f);
    float wb = w / (db > 0.f ? db : 1.f);

    const float4* xin4 = reinterpret_cast<const float4*>(g_xin);

    float4 a = xin4[(size_t)s * 16 + l];
    red_add4(&g_ofob[(size_t)t * 128 + l * 4], a.x * wf, a.y * wf, a.z * wf, a.w * wf);

    float4 b = xin4[(size_t)t * 16 + l];
    red_add4(&g_ofob[(size_t)s * 128 + 64 + l * 4], b.x * wb, b.y * wb, b.z * wb, b.w * wb);
}

// ---------------------------------------------------------------------------
// Generic dense stage: C[g, coff + 0..OC) = A[g, 0..128) @ W[128,OC] + bias
// Block: 256 threads, SUBS*NPT nodes per block. Thread: NPT nodes x 4 cols.
// sV stride 129 => bank = node (mod 32) => conflict-free.
// ---------------------------------------------------------------------------
template <int OC, int SUBS, int NPT>
__global__ void gemm_kernel(const float* __restrict__ A, const float* __restrict__ W,
                            const float* __restrict__ B, float* __restrict__ C,
                            int N, int cstride, int coff) {
    constexpr int NT = SUBS * NPT;
    constexpr int Q = OC / 4;
    extern __shared__ float sm[];
    float* sW = sm;                 // 128*OC
    float* sB = sW + 128 * OC;      // OC
    float* sV = sB + OC;            // NT*129

    int tid = threadIdx.x;
    for (int idx = tid; idx < 128 * OC; idx += 256) sW[idx] = W[idx];
    if (tid < OC) sB[tid] = B[tid];

    int node0 = blockIdx.x * NT;
    for (int idx = tid; idx < NT * 128; idx += 256) {
        int n = idx >> 7, i = idx & 127;
        int g = node0 + n;
        sV[n * 129 + i] = (g < N) ? A[(size_t)g * 128 + i] : 0.f;
    }
    __syncthreads();

    int c4 = tid % Q;
    int sub = tid / Q;
    if (sub < SUBS) {
        const float4* sW4 = reinterpret_cast<const float4*>(sW);
        float4 bb = reinterpret_cast<const float4*>(sB)[c4];
        float4 acc[NPT];
        #pragma unroll
        for (int k = 0; k < NPT; k++) acc[k] = bb;

        #pragma unroll 4
        for (int i = 0; i < 128; i++) {
            float4 w = sW4[i * Q + c4];
            #pragma unroll
            for (int k = 0; k < NPT; k++) {
                float xv = sV[(sub * NPT + k) * 129 + i];
                acc[k].x += xv * w.x; acc[k].y += xv * w.y;
                acc[k].z += xv * w.z; acc[k].w += xv * w.w;
            }
        }
        #pragma unroll
        for (int k = 0; k < NPT; k++) {
            int g = node0 + sub * NPT + k;
            if (g < N) {
                float* dst = C + (size_t)g * cstride + coff + c4 * 4;
                *reinterpret_cast<float4*>(dst) = acc[k];
            }
        }
    }
}

// ---------------------------------------------------------------------------
// Post: softplus(sigma), softmax(pi over K=32), write gmm_out. One warp/node.
// ---------------------------------------------------------------------------
__global__ void post_kernel(float* __restrict__ out, int N) {
    int gwarp = (blockIdx.x * blockDim.x + threadIdx.x) >> 5;
    int lane = threadIdx.x & 31;
    if (gwarp >= N) return;
    const float* r = g_raw + (size_t)gwarp * 96;
    float mu = r[lane];
    float sg = r[32 + lane];
    float pl = r[64 + lane];

    float sp = (sg > 20.f) ? sg : log1pf(expf(sg));

    float m = pl;
    #pragma unroll
    for (int o = 16; o; o >>= 1) m = fmaxf(m, __shfl_xor_sync(0xFFFFFFFFu, m, o));
    float e = expf(pl - m);
    float ssum = e;
    #pragma unroll
    for (int o = 16; o; o >>= 1) ssum += __shfl_xor_sync(0xFFFFFFFFu, ssum, o);
    float pi = e / ssum;

    float* o = out + (size_t)gwarp * 96;
    o[lane]      = mu;
    o[32 + lane] = sp;
    o[64 + lane] = pi;
}

// ---------------------------------------------------------------------------
// Launcher
// ---------------------------------------------------------------------------
extern "C" void kernel_launch(void* const* d_in, const int* in_sizes, int n_in,
                              void* d_out, int out_size) {
    const float* x   = (const float*)d_in[0];
    const float* xh  = (const float*)d_in[1];
    const float* h   = (const float*)d_in[2];
    const int*   ei  = (const int*)  d_in[3];
    const float* ew  = (const float*)d_in[4];
    const float* Win = (const float*)d_in[5];
    const float* bin = (const float*)d_in[6];
    const float* Wf  = (const float*)d_in[7];
    const float* bf  = (const float*)d_in[8];
    const float* Wmu = (const float*)d_in[9];
    const float* bmu = (const float*)d_in[10];
    const float* Wsg = (const float*)d_in[11];
    const float* bsg = (const float*)d_in[12];
    const float* Wpi = (const float*)d_in[13];
    const float* bpi = (const float*)d_in[14];

    int N = in_sizes[0];             // x is [N, 1]
    int E = in_sizes[3] / 2;         // edge_index is [2, E]
    if (N > MAXN) N = MAXN;
    if (E > MAXE) E = MAXE;
    float* out = (float*)d_out;

    void *p_ofob, *p_degf, *p_degb, *p_out1, *p_raw, *p_Whead, *p_bhead;
    cudaGetSymbolAddress(&p_ofob,  g_ofob);
    cudaGetSymbolAddress(&p_degf,  g_degf);
    cudaGetSymbolAddress(&p_degb,  g_degb);
    cudaGetSymbolAddress(&p_out1,  g_out1);
    cudaGetSymbolAddress(&p_raw,   g_raw);
    cudaGetSymbolAddress(&p_Whead, g_Whead);
    cudaGetSymbolAddress(&p_bhead, g_bhead);

    cudaMemsetAsync(p_ofob, 0, (size_t)N * 128 * sizeof(float));
    cudaMemsetAsync(p_degf, 0, (size_t)N * sizeof(float));
    cudaMemsetAsync(p_degb, 0, (size_t)N * sizeof(float));

    pack_head_kernel<<<(128 * 32 + 255) / 256, 256>>>(Wmu, bmu, Wsg, bsg, Wpi, bpi);

    // 1. input projection
    size_t sh_proj = (size_t)(161 * 64 + 64 + 32 * 163) * sizeof(float);
    cudaFuncSetAttribute(proj_kernel, cudaFuncAttributeMaxDynamicSharedMemorySize, (int)sh_proj);
    proj_kernel<<<(N + 31) / 32, 256, sh_proj>>>(x, xh, h, Win, bin, N);

    // 2. diffusion
    degree_kernel<<<(E + 255) / 256, 256>>>(ei, ew, E);
    scatter_kernel<<<(E + 15) / 16, 256>>>(ei, ew, E);

    // 3. filter GEMM: g_ofob[N,128] @ W_filt[128,64] -> g_out1 cols 0..63
    size_t shA = (size_t)(128 * 64 + 64 + 32 * 129) * sizeof(float);
    cudaFuncSetAttribute(gemm_kernel<64, 16, 2>, cudaFuncAttributeMaxDynamicSharedMemorySize, (int)shA);
    gemm_kernel<64, 16, 2><<<(N + 31) / 32, 256, shA>>>(
        (const float*)p_ofob, Wf, bf, (float*)p_out1, N, 128, 0);

    // 4. head GEMM: g_out1[N,128] @ W_head[128,96] -> g_raw
    size_t shB = (size_t)(128 * 96 + 96 + 30 * 129) * sizeof(float);
    cudaFuncSetAttribute(gemm_kernel<96, 10, 3>, cudaFuncAttributeMaxDynamicSharedMemorySize, (int)shB);
    gemm_kernel<96, 10, 3><<<(N + 29) / 30, 256, shB>>>(
        (const float*)p_out1, (const float*)p_Whead, (const float*)p_bhead,
        (float*)p_raw, N, 96, 0);

    // 5. activations + gmm_out
    post_kernel<<<((size_t)N * 32 + 255) / 256, 256>>>(out, N);

    // 6. out1 and h passthrough outputs
    size_t off1 = (size_t)N * 96;
    size_t off2 = off1 + (size_t)N * 128;
    if ((size_t)out_size >= off2)
        cudaMemcpyAsync(out + off1, p_out1, (size_t)N * 128 * sizeof(float),
                        cudaMemcpyDeviceToDevice);
    if ((size_t)out_size >= off2 + (size_t)N * 64)
        cudaMemcpyAsync(out + off2, h, (size_t)N * 64 * sizeof(float),
                        cudaMemcpyDeviceToDevice);
}